// round 10
// baseline (speedup 1.0000x reference)
#include <cuda_runtime.h>
#include <cuda_fp16.h>
#include <cstdint>

#define NSYMS  256
#define NSTEPS 8192
#define NCH    62
#define HID    16

// ===========================================================================
// fp16 B fragments for mma.m16n8k16 (market cols only; k=62,63 zeroed):
//   g_Bfrag16[(ks*8+nt)*32 + lane] = { h01, h89 }
// g_Wst[0..63] = W_eff[o][sym], g_Wst[64..127] = W_eff[o][t]  (fp32, exact)
// ===========================================================================
__device__ uint2 g_Bfrag16[4 * 8 * 32];
__device__ float g_Wst[128];

__global__ void build_weff(const float* __restrict__ W1h, const float* __restrict__ M1h,
                           const float* __restrict__ W2h, const float* __restrict__ M2h,
                           const float* __restrict__ W3h, const float* __restrict__ M3h) {
    __shared__ float W1[HID * 64];
    __shared__ float W2[HID * HID];
    __shared__ float W3[64 * HID];
    __shared__ float T2[HID * 64];
    __shared__ float Wt[64 * 64];   // [cin][o]
    const int tid = threadIdx.x;

    for (int i = tid; i < HID * 64; i += 256)
        W1[i] = tanhf(W1h[i]) * (1.0f / (1.0f + expf(-M1h[i])));
    for (int i = tid; i < HID * HID; i += 256)
        W2[i] = tanhf(W2h[i]) * (1.0f / (1.0f + expf(-M2h[i])));
    for (int i = tid; i < 64 * HID; i += 256)
        W3[i] = tanhf(W3h[i]) * (1.0f / (1.0f + expf(-M3h[i])));
    __syncthreads();

    for (int i = tid; i < HID * 64; i += 256) {
        int h = i >> 6, c = i & 63;
        float s = 0.0f;
#pragma unroll
        for (int k = 0; k < HID; k++) s += W2[h * HID + k] * W1[k * 64 + c];
        T2[i] = s;
    }
    __syncthreads();

    for (int i = tid; i < 64 * 64; i += 256) {
        int o = i >> 6, c = i & 63;
        float s = 0.0f;
#pragma unroll
        for (int k = 0; k < HID; k++) s += W3[o * HID + k] * T2[k * 64 + c];
        Wt[c * 64 + o] = s;
    }
    __syncthreads();

    for (int i = tid; i < 1024; i += 256) {
        int lane = i & 31, nt = (i >> 5) & 7, ks = i >> 8;
        int g = lane >> 2, q = lane & 3;
        int n = nt * 8 + g;
        int k0 = ks * 16 + 2 * q;
        float w[4];
#pragma unroll
        for (int j = 0; j < 4; j++) {
            int k = k0 + (j >> 1) * 8 + (j & 1);
            w[j] = (k < 62) ? Wt[(k + 2) * 64 + n] : 0.0f;
        }
        __half2 h01 = __floats2half2_rn(w[0], w[1]);
        __half2 h89 = __floats2half2_rn(w[2], w[3]);
        uint2 u;
        u.x = *reinterpret_cast<uint32_t*>(&h01);
        u.y = *reinterpret_cast<uint32_t*>(&h89);
        g_Bfrag16[i] = u;
    }
    for (int i = tid; i < 128; i += 256)
        g_Wst[i] = Wt[i];
}

// ===========================================================================
// PTX helpers
// ===========================================================================
__device__ __forceinline__ void mma16816h(float& d0, float& d1, float& d2, float& d3,
                                          uint32_t a0, uint32_t a1, uint32_t a2, uint32_t a3,
                                          uint32_t b0, uint32_t b1) {
    asm volatile("mma.sync.aligned.m16n8k16.row.col.f32.f16.f16.f32 "
                 "{%0,%1,%2,%3}, {%4,%5,%6,%7}, {%8,%9}, {%0,%1,%2,%3};"
                 : "+f"(d0), "+f"(d1), "+f"(d2), "+f"(d3)
                 : "r"(a0), "r"(a1), "r"(a2), "r"(a3), "r"(b0), "r"(b1));
}
__device__ __forceinline__ void cvt_split_h(float x, float y, uint32_t& h, uint32_t& l) {
    __half2 h2 = __floats2half2_rn(x, y);
    float2 hf = __half22float2(h2);
    __half2 l2 = __floats2half2_rn(x - hf.x, y - hf.y);
    h = *reinterpret_cast<uint32_t*>(&h2);
    l = *reinterpret_cast<uint32_t*>(&l2);
}
__device__ __forceinline__ uint32_t smem_u32(const void* p) {
    uint32_t a;
    asm("{ .reg .u64 t; cvta.to.shared.u64 t, %1; cvt.u32.u64 %0, t; }" : "=r"(a) : "l"(p));
    return a;
}
__device__ __forceinline__ void mbar_init(uint32_t mbar, uint32_t cnt) {
    asm volatile("mbarrier.init.shared.b64 [%0], %1;" :: "r"(mbar), "r"(cnt) : "memory");
}
__device__ __forceinline__ void mbar_expect_tx(uint32_t mbar, uint32_t bytes) {
    asm volatile("mbarrier.arrive.expect_tx.shared.b64 _, [%0], %1;" :: "r"(mbar), "r"(bytes) : "memory");
}
__device__ __forceinline__ void mbar_wait(uint32_t mbar, uint32_t parity) {
    asm volatile("{\n\t.reg .pred P1;\n\tWL_%=:\n\t"
                 "mbarrier.try_wait.parity.acquire.cta.shared::cta.b64 P1, [%0], %1, 0x989680;\n\t"
                 "@P1 bra.uni WD_%=;\n\tbra.uni WL_%=;\n\tWD_%=:\n\t}"
                 :: "r"(mbar), "r"(parity) : "memory");
}
__device__ __forceinline__ void bulk_g2s(uint32_t dst, const void* src, uint32_t bytes, uint32_t mbar) {
    asm volatile("cp.async.bulk.shared::cta.global.mbarrier::complete_tx::bytes [%0], [%1], %2, [%3];"
                 :: "r"(dst), "l"(src), "r"(bytes), "r"(mbar) : "memory");
}
#define FENCE_ASYNC() asm volatile("fence.proxy.async.shared::cta;" ::: "memory")
#define LDS64F(f0, f1, a) \
    asm volatile("ld.shared.v2.f32 {%0, %1}, [%2];" : "=f"(f0), "=f"(f1) : "r"(a))
#define STS64F(a, f0, f1) \
    asm volatile("st.shared.v2.f32 [%0], {%1, %2};" :: "r"(a), "f"(f0), "f"(f1) : "memory")
#define LDS128F(f0, f1, f2, f3, a) \
    asm volatile("ld.shared.v4.f32 {%0, %1, %2, %3}, [%4];" : "=f"(f0), "=f"(f1), "=f"(f2), "=f"(f3) : "r"(a))

// ===========================================================================
// Main kernel: bulk-copy double-buffered pipeline, fp16 MMA, 16 warps.
//   CTA: 512 thr, ITERS=8 slabs x 128 rows = 1024 rows; grid 2048.
//   Warp (rg = warp>>1, nh = warp&1): rows rg*16..+16 of slab, outs nh*32..+32.
//   A staged fp32 in smem, contiguous 248B rows (one bulk copy per slab).
// ===========================================================================
#define ITERS      8
#define SLAB_ROWS  128
#define ROW_BYTES  248                         // 62 * 4  (the R8 bug: was 992)
#define SLAB_BYTES (SLAB_ROWS * ROW_BYTES)     // 31744, multiple of 16 ok
#define SM_EPI     (2 * SLAB_BYTES)            // 63488: 16 x 2KB warp tiles
#define SM_SCORR   (SM_EPI + 32768)            // 96256: 128 floats
#define SM_MBAR    (SM_SCORR + 512)            // 96768: 2 mbarriers
#define SM_TOTAL   (SM_MBAR + 128)

__global__ void __launch_bounds__(512, 1)
encode_kernel(const float* __restrict__ market, float* __restrict__ out) {
    extern __shared__ char smem[];
    const uint32_t sb = smem_u32(smem);
    const int tid  = threadIdx.x;
    const int warp = tid >> 5;
    const int lane = tid & 31;
    const int g  = lane >> 2;    // 0..7
    const int q  = lane & 3;     // 0..3
    const int rg = warp >> 1;    // 0..7 row group (16 rows)
    const int nh = warp & 1;     // n half (32 outs)

    // ---- B fragments: 32 regs (this warp's 4 n-tiles)
    uint32_t BH0[16], BH1[16];
#pragma unroll
    for (int ks = 0; ks < 4; ks++)
#pragma unroll
        for (int nt = 0; nt < 4; nt++) {
            uint2 u = g_Bfrag16[(ks * 8 + nh * 4 + nt) * 32 + lane];
            BH0[ks * 4 + nt] = u.x;
            BH1[ks * 4 + nt] = u.y;
        }

    const long long cta_row0 = (long long)blockIdx.x * (ITERS * SLAB_ROWS);
    const float sval = (float)(cta_row0 >> 13);   // 8192 % 1024 == 0: one symbol/CTA
    const int   tcta = (int)(cta_row0 & (NSTEPS - 1));
    const char* srcbase = (const char*)market + cta_row0 * ROW_BYTES;

    if (tid < 64) {
        ((float*)(smem + SM_SCORR))[tid]      = sval * g_Wst[tid];
        ((float*)(smem + SM_SCORR))[64 + tid] = g_Wst[64 + tid];
    }
    if (tid == 0) {
        mbar_init(sb + SM_MBAR, 1);
        mbar_init(sb + SM_MBAR + 8, 1);
        FENCE_ASYNC();
    }
    __syncthreads();

    // ---- issue slabs 0,1 (one bulk copy each)
    if (tid == 0) {
#pragma unroll
        for (int s = 0; s < 2; s++) {
            uint32_t mb = sb + SM_MBAR + s * 8;
            mbar_expect_tx(mb, SLAB_BYTES);
            bulk_g2s(sb + s * SLAB_BYTES, srcbase + (size_t)s * SLAB_BYTES, SLAB_BYTES, mb);
        }
    }

    const uint32_t wtile = sb + SM_EPI + warp * 2048;   // 16 rows x 32 floats
    const float* scorr = (const float*)(smem + SM_SCORR);

#pragma unroll 1
    for (int it = 0; it < ITERS; it++) {
        mbar_wait(sb + SM_MBAR + (it & 1) * 8, (it >> 1) & 1);

        const uint32_t ab = sb + (it & 1) * SLAB_BYTES + (rg * 16 + g) * ROW_BYTES;

        // ---- LDS fragments + convert + MMA (fp16 2-term: (Ah+Al)*Bh)
        float acc[16];
#pragma unroll
        for (int i = 0; i < 16; i++) acc[i] = 0.0f;

#pragma unroll
        for (int ks = 0; ks < 4; ks++) {
            const uint32_t c0b = (uint32_t)(ks * 16 + 2 * q) * 4;
            float2 v0, v1, v2, v3;
            LDS64F(v0.x, v0.y, ab + c0b);                       // row g,   pair0
            LDS64F(v2.x, v2.y, ab + 8 * ROW_BYTES + c0b);       // row g+8, pair0
            if (ks == 3 && q == 3) {
                v1 = make_float2(0.0f, 0.0f);                   // k=62,63: affine
                v3 = make_float2(0.0f, 0.0f);
            } else {
                LDS64F(v1.x, v1.y, ab + c0b + 32);              // row g,   pair1
                LDS64F(v3.x, v3.y, ab + 8 * ROW_BYTES + c0b + 32);
            }
            uint32_t ah0, ah1, ah2, ah3, al0, al1, al2, al3;
            cvt_split_h(v0.x, v0.y, ah0, al0);
            cvt_split_h(v2.x, v2.y, ah1, al1);
            cvt_split_h(v1.x, v1.y, ah2, al2);
            cvt_split_h(v3.x, v3.y, ah3, al3);
#pragma unroll
            for (int nt = 0; nt < 4; nt++) {
                const int bi = ks * 4 + nt;
                mma16816h(acc[nt*4+0], acc[nt*4+1], acc[nt*4+2], acc[nt*4+3],
                          ah0, ah1, ah2, ah3, BH0[bi], BH1[bi]);
                mma16816h(acc[nt*4+0], acc[nt*4+1], acc[nt*4+2], acc[nt*4+3],
                          al0, al1, al2, al3, BH0[bi], BH1[bi]);
            }
        }
        __syncthreads();   // all warps done reading this stage buffer

        // ---- refill this buffer with slab it+2 (overlaps epilogue + next MMA)
        if (it + 2 < ITERS && tid == 0) {
            uint32_t mb = sb + SM_MBAR + (it & 1) * 8;
            mbar_expect_tx(mb, SLAB_BYTES);
            bulk_g2s(sb + (it & 1) * SLAB_BYTES,
                     srcbase + (size_t)(it + 2) * SLAB_BYTES, SLAB_BYTES, mb);
        }

        // ---- epilogue: fragments -> per-warp swizzled tile (16 x 8 float4)
        // phys_f4 = f4 ^ (row & 7)
        {
            const int qhi = q >> 1, qlo = q & 1;
#pragma unroll
            for (int nt = 0; nt < 4; nt++) {
                uint32_t f4 = (uint32_t)(2 * nt + qhi);
                uint32_t ph = f4 ^ (uint32_t)g;   // (g+8)&7 == g: same perm both rows
                STS64F(wtile + g * 128 + ph * 16 + qlo * 8,       acc[nt*4+0], acc[nt*4+1]);
                STS64F(wtile + (g + 8) * 128 + ph * 16 + qlo * 8, acc[nt*4+2], acc[nt*4+3]);
            }
        }
        __syncwarp();

        // ---- + exact affine(sym, t), coalesced stores (1 full line per row)
        {
            float* obase = out + (cta_row0 + (long long)it * SLAB_ROWS + rg * 16) * 64 + nh * 32;
            const float tbase = (float)(tcta + it * SLAB_ROWS + rg * 16);
#pragma unroll
            for (int rnd = 0; rnd < 4; rnd++) {
                int row = rnd * 4 + (lane >> 3);
                int f4  = lane & 7;
                uint32_t ph = (uint32_t)(f4 ^ (row & 7));
                float f0, f1, f2, f3;
                LDS128F(f0, f1, f2, f3, wtile + row * 128 + ph * 16);
                int col = nh * 32 + f4 * 4;
                float4 cr = *(const float4*)(scorr + col);
                float4 wt = *(const float4*)(scorr + 64 + col);
                float tv = tbase + (float)row;
                f0 += cr.x + tv * wt.x;
                f1 += cr.y + tv * wt.y;
                f2 += cr.z + tv * wt.z;
                f3 += cr.w + tv * wt.w;
                *(float4*)(obase + row * 64 + f4 * 4) = make_float4(f0, f1, f2, f3);
            }
        }
        __syncwarp();
    }
}

// ---------------------------------------------------------------------------
extern "C" void kernel_launch(void* const* d_in, const int* in_sizes, int n_in,
                              void* d_out, int out_size) {
    const float* market = (const float*)d_in[0];
    build_weff<<<1, 256>>>((const float*)d_in[1], (const float*)d_in[2],
                           (const float*)d_in[3], (const float*)d_in[4],
                           (const float*)d_in[5], (const float*)d_in[6]);

    cudaFuncSetAttribute((const void*)encode_kernel,
                         cudaFuncAttributeMaxDynamicSharedMemorySize, SM_TOTAL);
    const int nblocks = (NSYMS * NSTEPS) / (ITERS * SLAB_ROWS);   // 2048
    encode_kernel<<<nblocks, 512, SM_TOTAL>>>(market, (float*)d_out);
}